// round 16
// baseline (speedup 1.0000x reference)
#include <cuda_runtime.h>
#include <cuda_bf16.h>
#include <cstdint>

// Problem constants
#define BB   256
#define TT   512
#define IND  128
#define HID  100
#define G4   400          // 4*HID
#define MTOT (BB*TT)      // 131072

// ---------------- device scratch (static globals; no runtime alloc) -------------
__device__ float g_WihT[IND * G4];          // [k][g]
__device__ float g_bias[G4];                // bih + bhh
__device__ float g_pre[(MTOT + 2) * G4];    // [m][g] input projection (+2 rows pad)

// ---------------- f32x2 packed helpers (Blackwell) ------------------------------
__device__ __forceinline__ unsigned long long fma2(unsigned long long a,
                                                   unsigned long long b,
                                                   unsigned long long c) {
    unsigned long long d;
    asm("fma.rn.f32x2 %0, %1, %2, %3;" : "=l"(d) : "l"(a), "l"(b), "l"(c));
    return d;
}
__device__ __forceinline__ unsigned long long pack2(float lo, float hi) {
    unsigned long long d;
    asm("mov.b64 %0, {%1, %2};" : "=l"(d) : "f"(lo), "f"(hi));
    return d;
}
__device__ __forceinline__ float2 unpack2(unsigned long long v) {
    float lo, hi;
    asm("mov.b64 {%0, %1}, %2;" : "=f"(lo), "=f"(hi) : "l"(v));
    return make_float2(lo, hi);
}

// ---------------- hardware tanh activations (sm_75+) -----------------------------
__device__ __forceinline__ float tanh_hw(float x) {
    float y;
    asm("tanh.approx.f32 %0, %1;" : "=f"(y) : "f"(x));
    return y;
}
__device__ __forceinline__ float sig_hw(float x) {
    return fmaf(tanh_hw(0.5f * x), 0.5f, 0.5f);
}

// ---------------- cp.async helpers ------------------------------------------------
__device__ __forceinline__ void cp_async16(void* smem_dst, const void* gmem_src) {
    uint32_t s = (uint32_t)__cvta_generic_to_shared(smem_dst);
    asm volatile("cp.async.ca.shared.global [%0], [%1], 16;" :: "r"(s), "l"(gmem_src));
}
__device__ __forceinline__ void cp_commit() {
    asm volatile("cp.async.commit_group;");
}
__device__ __forceinline__ void cp_wait0() {
    asm volatile("cp.async.wait_group 0;");
}

// ================= K-prep: WihT + fused bias =====================================
__global__ void prep_kernel(const float* __restrict__ Wih,
                            const float* __restrict__ bih,
                            const float* __restrict__ bhh) {
    int idx = blockIdx.x * 256 + threadIdx.x;
    if (idx < G4 * IND) {
        int g = idx / IND, k = idx - g * IND;
        g_WihT[k * G4 + g] = Wih[idx];
    }
    if (idx < G4) g_bias[idx] = bih[idx] + bhh[idx];
}

// ================= K1: pre = x @ WihT + bias — 4-stage cp.async pipeline =========
// (byte-identical to the r13/r15-passing version)
__global__ void __launch_bounds__(416, 2) gemm_pre_kernel(const float* __restrict__ x) {
    __shared__ __align__(16) float xs[2][32 * 68];    // [k][m]
    __shared__ __align__(16) float ws[2][32 * 108];   // [k][g]

    int tid = threadIdx.x;
    int m0 = blockIdx.x * 64;
    int g0 = blockIdx.y * 100;
    int ty = tid & 15;
    int tx = tid >> 4;

    int wi1 = tid + 416;
    int wk0 = tid / 25, wg0 = tid - 25 * wk0;
    int wk1 = wi1 / 25, wg1 = wi1 - 25 * wk1;
    int xr0 = tid >> 3, xc0 = tid & 7;
    int xr1 = (tid + 416) >> 3, xc1 = (tid + 416) & 7;

    unsigned long long acc[4][2];
#pragma unroll
    for (int r = 0; r < 4; r++) { acc[r][0] = 0ULL; acc[r][1] = 0ULL; }

    float4 fx0, fx1;

    {
        const float* wb = g_WihT + (size_t)0 * G4 + g0;
        cp_async16(&ws[0][wk0 * 108 + 4 * wg0], wb + (size_t)wk0 * G4 + 4 * wg0);
        if (wi1 < 800)
            cp_async16(&ws[0][wk1 * 108 + 4 * wg1], wb + (size_t)wk1 * G4 + 4 * wg1);
        cp_commit();
        fx0 = *(const float4*)&x[(size_t)(m0 + xr0) * IND + 4 * xc0];
        if (tid < 96)
            fx1 = *(const float4*)&x[(size_t)(m0 + xr1) * IND + 4 * xc1];
        xs[0][(4 * xc0 + 0) * 68 + xr0] = fx0.x;
        xs[0][(4 * xc0 + 1) * 68 + xr0] = fx0.y;
        xs[0][(4 * xc0 + 2) * 68 + xr0] = fx0.z;
        xs[0][(4 * xc0 + 3) * 68 + xr0] = fx0.w;
        if (tid < 96) {
            xs[0][(4 * xc1 + 0) * 68 + xr1] = fx1.x;
            xs[0][(4 * xc1 + 1) * 68 + xr1] = fx1.y;
            xs[0][(4 * xc1 + 2) * 68 + xr1] = fx1.z;
            xs[0][(4 * xc1 + 3) * 68 + xr1] = fx1.w;
        }
        cp_wait0();
    }
    __syncthreads();

#pragma unroll
    for (int s = 0; s < 4; s++) {
        int b = s & 1;
        if (s < 3) {
            const float* wb = g_WihT + (size_t)(32 * (s + 1)) * G4 + g0;
            cp_async16(&ws[b ^ 1][wk0 * 108 + 4 * wg0], wb + (size_t)wk0 * G4 + 4 * wg0);
            if (wi1 < 800)
                cp_async16(&ws[b ^ 1][wk1 * 108 + 4 * wg1], wb + (size_t)wk1 * G4 + 4 * wg1);
            cp_commit();
            fx0 = *(const float4*)&x[(size_t)(m0 + xr0) * IND + 32 * (s + 1) + 4 * xc0];
            if (tid < 96)
                fx1 = *(const float4*)&x[(size_t)(m0 + xr1) * IND + 32 * (s + 1) + 4 * xc1];
        }
        if (tx < 25) {
#pragma unroll
            for (int k = 0; k < 32; k++) {
                float4 xv = *(const float4*)&xs[b][k * 68 + 4 * ty];
                ulonglong2 wv = *(const ulonglong2*)&ws[b][k * 108 + 4 * tx];
                unsigned long long d0 = pack2(xv.x, xv.x);
                unsigned long long d1 = pack2(xv.y, xv.y);
                unsigned long long d2 = pack2(xv.z, xv.z);
                unsigned long long d3 = pack2(xv.w, xv.w);
                acc[0][0] = fma2(d0, wv.x, acc[0][0]);
                acc[0][1] = fma2(d0, wv.y, acc[0][1]);
                acc[1][0] = fma2(d1, wv.x, acc[1][0]);
                acc[1][1] = fma2(d1, wv.y, acc[1][1]);
                acc[2][0] = fma2(d2, wv.x, acc[2][0]);
                acc[2][1] = fma2(d2, wv.y, acc[2][1]);
                acc[3][0] = fma2(d3, wv.x, acc[3][0]);
                acc[3][1] = fma2(d3, wv.y, acc[3][1]);
            }
        }
        if (s < 3) {
            xs[b ^ 1][(4 * xc0 + 0) * 68 + xr0] = fx0.x;
            xs[b ^ 1][(4 * xc0 + 1) * 68 + xr0] = fx0.y;
            xs[b ^ 1][(4 * xc0 + 2) * 68 + xr0] = fx0.z;
            xs[b ^ 1][(4 * xc0 + 3) * 68 + xr0] = fx0.w;
            if (tid < 96) {
                xs[b ^ 1][(4 * xc1 + 0) * 68 + xr1] = fx1.x;
                xs[b ^ 1][(4 * xc1 + 1) * 68 + xr1] = fx1.y;
                xs[b ^ 1][(4 * xc1 + 2) * 68 + xr1] = fx1.z;
                xs[b ^ 1][(4 * xc1 + 3) * 68 + xr1] = fx1.w;
            }
        }
        cp_wait0();
        __syncthreads();
    }

    if (tx < 25) {
        float b0 = g_bias[g0 + 4 * tx + 0];
        float b1 = g_bias[g0 + 4 * tx + 1];
        float b2 = g_bias[g0 + 4 * tx + 2];
        float b3 = g_bias[g0 + 4 * tx + 3];
#pragma unroll
        for (int r = 0; r < 4; r++) {
            float2 e0 = unpack2(acc[r][0]);
            float2 e1 = unpack2(acc[r][1]);
            float4 o = make_float4(e0.x + b0, e0.y + b1, e1.x + b2, e1.y + b3);
            *(float4*)&g_pre[(size_t)(m0 + 4 * ty + r) * G4 + g0 + 4 * tx] = o;
        }
    }
}

// ================= K2: LSTM + head, 1 row/block, 2 CTAs/SM =======================
// 256 blocks x 400 threads. Thread q owns gate q's FULL Whh row (exactly 50
// packed regs; 100 floats = exactly 25 LDS.128 of h). No k-split -> no shfl.
// Two independent CTAs per SM decouple the barrier convoy: when one block's
// warps sit in their dependency chain / barrier, the co-resident block issues.
// Epilogue computes this row's head logits directly (head kernel eliminated).
__global__ void __launch_bounds__(400, 2) lstm_kernel(const float* __restrict__ Whh,
                                                      const float* __restrict__ Wo,
                                                      const float* __restrict__ bo,
                                                      const float* __restrict__ Wc,
                                                      const float* __restrict__ bc,
                                                      float* __restrict__ out) {
    __shared__ float h_sh[HID];        // 100 floats = 25 x 16B, exact
    __shared__ float gact[G4];
    __shared__ float emb[64];

    int tid = threadIdx.x;
    int row = blockIdx.x;
    int q = tid;

    // full Whh row in 50 packed registers
    unsigned long long Wp[50];
#pragma unroll
    for (int j = 0; j < 50; j++)
        Wp[j] = pack2(Whh[q * HID + 2 * j], Whh[q * HID + 2 * j + 1]);

    if (tid < HID) h_sh[tid] = 0.f;

    float c = 0.f, hloc = 0.f;

    const float* prep = g_pre + ((size_t)row * TT) * G4 + q;
    bool is_tanh_gate = (q >= 200 && q < 300);

    // depth-1 prefetch (~1 full step of latency cover; pad rows keep tail safe)
    float pf = __ldg(prep); prep += G4;

    const ulonglong2* hp = (const ulonglong2*)&h_sh[0];

    __syncthreads();

    for (int t = 0; t < TT; t++) {
        float pc = pf;
        pf = __ldg(prep); prep += G4;

        // two independent 12/13-deep x2 chains over 25 LDS.128
        unsigned long long a0 = 0ULL, a1 = 0ULL;
#pragma unroll
        for (int j = 0; j < 24; j += 2) {
            ulonglong2 hv0 = hp[j];
            ulonglong2 hv1 = hp[j + 1];
            a0 = fma2(hv0.x, Wp[2 * j], a0);
            a0 = fma2(hv0.y, Wp[2 * j + 1], a0);
            a1 = fma2(hv1.x, Wp[2 * j + 2], a1);
            a1 = fma2(hv1.y, Wp[2 * j + 3], a1);
        }
        {   // j = 24 tail
            ulonglong2 hv = hp[24];
            a0 = fma2(hv.x, Wp[48], a0);
            a1 = fma2(hv.y, Wp[49], a1);
        }
        float2 u0 = unpack2(a0);
        float2 u1 = unpack2(a1);
        float v = (u0.x + u0.y) + (u1.x + u1.y) + pc;
        gact[q] = is_tanh_gate ? tanh_hw(v) : sig_hw(v);

        __syncthreads();
        if (tid < HID) {
            float iv = gact[tid];
            float fv = gact[tid + 100];
            float gv = gact[tid + 200];
            float ov = gact[tid + 300];
            c = fv * c + iv * gv;
            hloc = ov * tanh_hw(c);
            h_sh[tid] = hloc;
        }
        __syncthreads();
    }

    // ---- fused head: emb = h@Wo^T + bo ; logits = emb@Wc^T + bc ----
    if (tid < 64) {
        float s = bo[tid];
#pragma unroll 4
        for (int j = 0; j < HID; j++) s += h_sh[j] * Wo[tid * HID + j];
        emb[tid] = s;
    }
    __syncthreads();
    if (tid < 10) {
        float s = bc[tid];
#pragma unroll
        for (int e = 0; e < 64; e++) s += emb[e] * Wc[tid * 64 + e];
        out[row * 10 + tid] = s;
    }
}

// ================= launch ========================================================
extern "C" void kernel_launch(void* const* d_in, const int* in_sizes, int n_in,
                              void* d_out, int out_size) {
    const float* x    = (const float*)d_in[0];
    const float* Wih0 = (const float*)d_in[1];
    const float* Whh0 = (const float*)d_in[2];
    const float* bih0 = (const float*)d_in[3];
    const float* bhh0 = (const float*)d_in[4];
    const float* Wo = (const float*)d_in[13];
    const float* bo = (const float*)d_in[14];
    const float* Wc = (const float*)d_in[15];
    const float* bc = (const float*)d_in[16];
    float* out = (float*)d_out;

    prep_kernel<<<200, 256>>>(Wih0, bih0, bhh0);
    gemm_pre_kernel<<<dim3(MTOT / 64, 4), 416>>>(x);
    lstm_kernel<<<BB, 400>>>(Whh0, Wo, bo, Wc, bc, out);
}

// round 17
// speedup vs baseline: 2.4178x; 2.4178x over previous
#include <cuda_runtime.h>
#include <cuda_bf16.h>
#include <cstdint>

// Problem constants
#define BB   256
#define TT   512
#define IND  128
#define HID  100
#define G4   400          // 4*HID
#define G4P  416          // padded gates (4 tiles x 104)
#define MTOT (BB*TT)      // 131072

// ---------------- device scratch (static globals; no runtime alloc) -------------
__device__ float g_bias[G4];                       // bih + bhh
__device__ float g_pre[(MTOT + 2) * G4];           // [m][g] (+2 rows prefetch pad)
__device__ float g_hfinal[BB * HID];
__device__ __nv_bfloat16 g_xhi[MTOT * IND];        // x split-hi  (33.5 MB)
__device__ __nv_bfloat16 g_xlo[MTOT * IND];        // x split-lo
__device__ __nv_bfloat16 g_whi[G4P * IND];         // Wih split-hi (padded, zero tail)
__device__ __nv_bfloat16 g_wlo[G4P * IND];

// ---------------- f32x2 packed helpers (lstm) ------------------------------------
__device__ __forceinline__ unsigned long long fma2(unsigned long long a,
                                                   unsigned long long b,
                                                   unsigned long long c) {
    unsigned long long d;
    asm("fma.rn.f32x2 %0, %1, %2, %3;" : "=l"(d) : "l"(a), "l"(b), "l"(c));
    return d;
}
__device__ __forceinline__ unsigned long long pack2(float lo, float hi) {
    unsigned long long d;
    asm("mov.b64 %0, {%1, %2};" : "=l"(d) : "f"(lo), "f"(hi));
    return d;
}
__device__ __forceinline__ float2 unpack2(unsigned long long v) {
    float lo, hi;
    asm("mov.b64 {%0, %1}, %2;" : "=f"(lo), "=f"(hi) : "l"(v));
    return make_float2(lo, hi);
}
__device__ __forceinline__ float tanh_hw(float x) {
    float y;
    asm("tanh.approx.f32 %0, %1;" : "=f"(y) : "f"(x));
    return y;
}
__device__ __forceinline__ float sig_hw(float x) {
    return fmaf(tanh_hw(0.5f * x), 0.5f, 0.5f);
}
__device__ __forceinline__ void cp_async16(void* smem_dst, const void* gmem_src) {
    uint32_t s = (uint32_t)__cvta_generic_to_shared(smem_dst);
    asm volatile("cp.async.ca.shared.global [%0], [%1], 16;" :: "r"(s), "l"(gmem_src));
}
__device__ __forceinline__ void cp_commit() { asm volatile("cp.async.commit_group;"); }

// ================= K-prep: bf16-split W + fused bias =============================
__global__ void prep_kernel(const float* __restrict__ Wih,
                            const float* __restrict__ bih,
                            const float* __restrict__ bhh) {
    int idx = blockIdx.x * 256 + threadIdx.x;     // grid 208 -> covers 53248
    if (idx < G4P * IND) {
        int g = idx >> 7;
        float w = (g < G4) ? Wih[idx - (g - g) * 0 + (g * IND + (idx & 127)) - idx + idx] : 0.f;
        // (note: for g<G4, padded layout == source layout since idx = g*128+k)
        if (g >= G4) w = 0.f; else w = Wih[idx];
        __nv_bfloat16 hi = __float2bfloat16(w);
        __nv_bfloat16 lo = __float2bfloat16(w - __bfloat162float(hi));
        g_whi[idx] = hi;
        g_wlo[idx] = lo;
    }
    if (idx < G4) g_bias[idx] = bih[idx] + bhh[idx];
}

// ================= K0: x -> bf16 hi/lo split =====================================
__global__ void convert_x_kernel(const float* __restrict__ x) {
    int i = blockIdx.x * 256 + threadIdx.x;       // grid 16384 -> 4.19M threads x4
    float4 v = *(const float4*)&x[(size_t)i * 4];
    __nv_bfloat16 h0 = __float2bfloat16(v.x), h1 = __float2bfloat16(v.y);
    __nv_bfloat16 h2 = __float2bfloat16(v.z), h3 = __float2bfloat16(v.w);
    __nv_bfloat162* ph = (__nv_bfloat162*)&g_xhi[(size_t)i * 4];
    ph[0] = __nv_bfloat162{h0, h1};
    ph[1] = __nv_bfloat162{h2, h3};
    __nv_bfloat162* pl = (__nv_bfloat162*)&g_xlo[(size_t)i * 4];
    pl[0] = __nv_bfloat162{__float2bfloat16(v.x - __bfloat162float(h0)),
                           __float2bfloat16(v.y - __bfloat162float(h1))};
    pl[1] = __nv_bfloat162{__float2bfloat16(v.z - __bfloat162float(h2)),
                           __float2bfloat16(v.w - __bfloat162float(h3))};
}

// ================= K1: pre = x @ Wih^T + bias — bf16-split mma.sync ==============
// Block: 128 threads (4 warps), tile M=64 x N=104 (padded gate space), K=128 in
// 8 double-buffered cp.async k16-slices. Each warp owns one m16 band x 13 n8
// tiles. 3 products per tile (xh*wh, xh*wl, xl*wh) accumulate fp32.
// Smem rows padded to 24 elems (48B) -> conflict-free frag LDS.32.
#define SAROW 24
__global__ void __launch_bounds__(128, 4) gemm_mma_kernel() {
    __shared__ __nv_bfloat16 sA[2][2][64 * SAROW];    // [buf][split][m][k16]
    __shared__ __nv_bfloat16 sB[2][2][104 * SAROW];   // [buf][split][n][k16]

    int tid = threadIdx.x;
    int lane = tid & 31;
    int warp = tid >> 5;
    int m0 = blockIdx.x * 64;
    int g0 = blockIdx.y * 104;        // padded gate base
    int band = warp * 16;
    int gq = lane >> 2;               // frag group id
    int t4 = lane & 3;

    float acc[13][4];
#pragma unroll
    for (int n = 0; n < 13; n++)
#pragma unroll
        for (int r = 0; r < 4; r++) acc[n][r] = 0.f;

    // ---- staging helper (inline twice) ----
    // A: 256 chunks (2 splits x 64 rows x 2 halves); B: 416 (2 x 104 x 2)
#define STAGE(buf, ks)                                                           \
    {                                                                            \
        int k0 = (ks) * 16;                                                      \
        for (int i = tid; i < 256; i += 128) {                                   \
            int s = i >> 7, j = i & 127, r = j >> 1, h = j & 1;                  \
            const __nv_bfloat16* src = (s ? g_xlo : g_xhi)                       \
                + (size_t)(m0 + r) * IND + k0 + h * 8;                           \
            cp_async16(&sA[buf][s][r * SAROW + h * 8], src);                     \
        }                                                                        \
        for (int i = tid; i < 416; i += 128) {                                   \
            int s = (i >= 208) ? 1 : 0, j = i - s * 208, r = j >> 1, h = j & 1;  \
            const __nv_bfloat16* src = (s ? g_wlo : g_whi)                       \
                + (size_t)(g0 + r) * IND + k0 + h * 8;                           \
            cp_async16(&sB[buf][s][r * SAROW + h * 8], src);                     \
        }                                                                        \
        cp_commit();                                                             \
    }

    STAGE(0, 0);
    asm volatile("cp.async.wait_group 0;");
    __syncthreads();

#pragma unroll
    for (int ks = 0; ks < 8; ks++) {
        int buf = ks & 1;
        if (ks < 7) STAGE(buf ^ 1, ks + 1);

        // A frags for this band, both splits
        uint32_t ah[4], al[4];
#pragma unroll
        for (int s = 0; s < 2; s++) {
            uint32_t* a = s ? al : ah;
            const __nv_bfloat16* base = sA[buf][s];
            a[0] = *(const uint32_t*)&base[(band + gq) * SAROW + 2 * t4];
            a[1] = *(const uint32_t*)&base[(band + gq + 8) * SAROW + 2 * t4];
            a[2] = *(const uint32_t*)&base[(band + gq) * SAROW + 8 + 2 * t4];
            a[3] = *(const uint32_t*)&base[(band + gq + 8) * SAROW + 8 + 2 * t4];
        }
#pragma unroll
        for (int nt = 0; nt < 13; nt++) {
            int nrow = nt * 8 + gq;
            uint32_t bh0 = *(const uint32_t*)&sB[buf][0][nrow * SAROW + 2 * t4];
            uint32_t bh1 = *(const uint32_t*)&sB[buf][0][nrow * SAROW + 8 + 2 * t4];
            uint32_t bl0 = *(const uint32_t*)&sB[buf][1][nrow * SAROW + 2 * t4];
            uint32_t bl1 = *(const uint32_t*)&sB[buf][1][nrow * SAROW + 8 + 2 * t4];
            float* d = acc[nt];
            asm volatile(
                "mma.sync.aligned.m16n8k16.row.col.f32.bf16.bf16.f32 "
                "{%0,%1,%2,%3},{%4,%5,%6,%7},{%8,%9},{%0,%1,%2,%3};"
                : "+f"(d[0]), "+f"(d[1]), "+f"(d[2]), "+f"(d[3])
                : "r"(ah[0]), "r"(ah[1]), "r"(ah[2]), "r"(ah[3]), "r"(bh0), "r"(bh1));
            asm volatile(
                "mma.sync.aligned.m16n8k16.row.col.f32.bf16.bf16.f32 "
                "{%0,%1,%2,%3},{%4,%5,%6,%7},{%8,%9},{%0,%1,%2,%3};"
                : "+f"(d[0]), "+f"(d[1]), "+f"(d[2]), "+f"(d[3])
                : "r"(ah[0]), "r"(ah[1]), "r"(ah[2]), "r"(ah[3]), "r"(bl0), "r"(bl1));
            asm volatile(
                "mma.sync.aligned.m16n8k16.row.col.f32.bf16.bf16.f32 "
                "{%0,%1,%2,%3},{%4,%5,%6,%7},{%8,%9},{%0,%1,%2,%3};"
                : "+f"(d[0]), "+f"(d[1]), "+f"(d[2]), "+f"(d[3])
                : "r"(al[0]), "r"(al[1]), "r"(al[2]), "r"(al[3]), "r"(bh0), "r"(bh1));
        }
        __syncthreads();                       // compute(buf) done before restage
        if (ks < 7) {
            asm volatile("cp.async.wait_group 0;");
            __syncthreads();
        }
    }

    // ---- epilogue: add bias, store fp32 (guard padded gates) ----
#pragma unroll
    for (int nt = 0; nt < 13; nt++) {
        int g = g0 + nt * 8 + 2 * t4;          // even, pairs never straddle 400
        if (g < G4) {
            float2 bv = *(const float2*)&g_bias[g];
            int mA = m0 + band + gq;
            *(float2*)&g_pre[(size_t)mA * G4 + g] =
                make_float2(acc[nt][0] + bv.x, acc[nt][1] + bv.y);
            *(float2*)&g_pre[(size_t)(mA + 8) * G4 + g] =
                make_float2(acc[nt][2] + bv.x, acc[nt][3] + bv.y);
        }
    }
}
#undef STAGE

// ================= K2: LSTM recurrence — split-K (r15-passing, verbatim) =========
__global__ void __launch_bounds__(800, 1) lstm_kernel(const float* __restrict__ Whh) {
    __shared__ float h_sh[2][112];
    __shared__ float gact[2][G4];

    int tid = threadIdx.x;
    int r0 = blockIdx.x * 2;
    int q = tid >> 1;
    int half = tid & 1;

    unsigned long long Wp[26];
#pragma unroll
    for (int j = 0; j < 26; j++) {
        int k = half * 52 + 2 * j;
        float lo = (k < HID)     ? Whh[q * HID + k]     : 0.f;
        float hi = (k + 1 < HID) ? Whh[q * HID + k + 1] : 0.f;
        Wp[j] = pack2(lo, hi);
    }
    if (tid < 224) ((float*)h_sh)[tid] = 0.f;

    float c = 0.f, hloc = 0.f;

    const float* prep = g_pre + ((size_t)(r0 + half) * TT) * G4 + q;
    bool is_tanh_gate = (q >= 200 && q < 300);

    float pf = __ldg(prep); prep += G4;

    const ulonglong2* hp0 = (const ulonglong2*)&h_sh[0][half * 52];
    const ulonglong2* hp1 = (const ulonglong2*)&h_sh[1][half * 52];

    __syncthreads();

    for (int t = 0; t < TT; t++) {
        float pc = pf;
        pf = __ldg(prep); prep += G4;

        unsigned long long a0 = 0ULL, a1 = 0ULL;
#pragma unroll
        for (int j = 0; j < 13; j++) {
            ulonglong2 hv0 = hp0[j];
            ulonglong2 hv1 = hp1[j];
            a0 = fma2(hv0.x, Wp[2 * j], a0);
            a0 = fma2(hv0.y, Wp[2 * j + 1], a0);
            a1 = fma2(hv1.x, Wp[2 * j], a1);
            a1 = fma2(hv1.y, Wp[2 * j + 1], a1);
        }
        float2 u0 = unpack2(a0);
        float2 u1 = unpack2(a1);
        float s0 = u0.x + u0.y;
        float s1 = u1.x + u1.y;
        s0 += __shfl_xor_sync(0xFFFFFFFFu, s0, 1);
        s1 += __shfl_xor_sync(0xFFFFFFFFu, s1, 1);
        float v = (half ? s1 : s0) + pc;
        gact[half][q] = is_tanh_gate ? tanh_hw(v) : sig_hw(v);

        __syncthreads();
        if (tid >= 600) {
            int i2 = tid - 600;
            int pr = i2 / 100;
            int pj = i2 - pr * 100;
            float iv = gact[pr][pj];
            float fv = gact[pr][pj + 100];
            float gv = gact[pr][pj + 200];
            float ov = gact[pr][pj + 300];
            c = fv * c + iv * gv;
            hloc = ov * tanh_hw(c);
            h_sh[pr][pj] = hloc;
        }
        __syncthreads();
    }

    if (tid >= 600) {
        int i2 = tid - 600;
        int pr = i2 / 100;
        int pj = i2 - pr * 100;
        g_hfinal[(r0 + pr) * HID + pj] = hloc;
    }
}

// ================= K3: head (r15-passing, verbatim) ==============================
__global__ void head_kernel(const float* __restrict__ Wo, const float* __restrict__ bo,
                            const float* __restrict__ Wc, const float* __restrict__ bc,
                            float* __restrict__ out) {
    __shared__ float h[HID];
    __shared__ float emb[64];
    int b = blockIdx.x, tid = threadIdx.x;
    if (tid < HID) h[tid] = g_hfinal[b * HID + tid];
    __syncthreads();
    if (tid < 64) {
        float s = bo[tid];
#pragma unroll 4
        for (int j = 0; j < HID; j++) s += h[j] * Wo[tid * HID + j];
        emb[tid] = s;
    }
    __syncthreads();
    if (tid < 10) {
        float s = bc[tid];
#pragma unroll
        for (int e = 0; e < 64; e++) s += emb[e] * Wc[tid * 64 + e];
        out[b * 10 + tid] = s;
    }
}

// ================= launch ========================================================
extern "C" void kernel_launch(void* const* d_in, const int* in_sizes, int n_in,
                              void* d_out, int out_size) {
    const float* x    = (const float*)d_in[0];
    const float* Wih0 = (const float*)d_in[1];
    const float* Whh0 = (const float*)d_in[2];
    const float* bih0 = (const float*)d_in[3];
    const float* bhh0 = (const float*)d_in[4];
    const float* Wo = (const float*)d_in[13];
    const float* bo = (const float*)d_in[14];
    const float* Wc = (const float*)d_in[15];
    const float* bc = (const float*)d_in[16];
    float* out = (float*)d_out;

    prep_kernel<<<208, 256>>>(Wih0, bih0, bhh0);
    convert_x_kernel<<<MTOT * IND / 1024, 256>>>(x);
    gemm_mma_kernel<<<dim3(MTOT / 64, 4), 128>>>();
    lstm_kernel<<<128, 800>>>(Whh0);
    head_kernel<<<BB, 128>>>(Wo, bo, Wc, bc, out);
}